// round 5
// baseline (speedup 1.0000x reference)
#include <cuda_runtime.h>
#include <stdint.h>

// ---------------------------------------------------------------------------
// BatchTopK: global top-(32*T) over masked [B,S,F], scatter relu'd winners,
// EMA threshold. 4-launch pipeline:
//   KMS  : fused stream — zero output (streaming stores), read eligible x once
//          (streaming loads), warp-ballot compaction of keys >= pivot(2.25),
//          1023-bin histogram of candidate bins
//   K2FB : 1 block — suffix-scan hist -> b1 + need; if the pivot assumption
//          failed, run the exact single-block fallback (histogram + recompact)
//   K4a  : barrier-free split: bin>b1 -> scatter winners; bin==b1 -> cand2+h2
//   K4b  : finish radix select in bin b1, ties by lowest index, EMA threshold,
//          then RESET all persistent state for the next graph replay
// ---------------------------------------------------------------------------

#define NBIN 4096
#define PIVOT_KEY 0xC0100000u   // f2key(2.25f)
#define PIVOT_BIN 3073          // PIVOT_KEY >> 20
#define NH (NBIN - PIVOT_BIN)   // 1023 hist bins
#define KEY_ZERO  0x80000000u   // f2key(+0.0f)
#define CAP  (1u << 22)
#define CAP2 (1u << 20)
#define MAXTIE 4096
#define WBUF_CAP 96
#define WBUF_FLUSH 64

__device__ unsigned g_hist[NBIN];
__device__ unsigned g_h2[256];
__device__ int      g_b1 = -1;
__device__ unsigned g_need;
__device__ unsigned g_ncand;
__device__ unsigned g_ncand2;
__device__ unsigned g_flag;
__device__ unsigned g_minpos = 0xFFFFFFFFu;
__device__ uint2    g_cand[CAP];
__device__ uint2    g_cand2[CAP2];

__device__ __forceinline__ unsigned f2key(unsigned u) {
    unsigned m = ((unsigned)((int)u >> 31)) | 0x80000000u;
    return u ^ m;
}
__device__ __forceinline__ float key2f(unsigned k) {
    unsigned u = (k & 0x80000000u) ? (k ^ 0x80000000u) : ~k;
    return __uint_as_float(u);
}

// ------------------------- KMS: fused zero + scan + compact + histogram
// blockDim MUST be 256 (8 warps).
__global__ void kms_stream(const float* __restrict__ x,
                           const int* __restrict__ mask,
                           float* __restrict__ out, int T, int F) {
    __shared__ unsigned shist[NH];
    __shared__ uint2 wbuf[8][WBUF_CAP];
    __shared__ unsigned wc[8];
    __shared__ unsigned gbs;
    const int tid = threadIdx.x;
    const int lane = tid & 31;
    const int w = tid >> 5;
    for (int i = tid; i < NH; i += blockDim.x) shist[i] = 0u;
    __syncthreads();

    const int f4 = F >> 2;
    const float4 z4 = make_float4(0.f, 0.f, 0.f, 0.f);
    unsigned cnt = 0u;   // warp-uniform count in wbuf[w]

#define KS_PUSH(KEY, GIDX, IS) do {                                           \
    unsigned bal = __ballot_sync(0xFFFFFFFFu, (IS));                          \
    if (bal) {                                                                \
        if (IS) {                                                             \
            unsigned r = __popc(bal & ((1u << lane) - 1u));                   \
            wbuf[w][cnt + r] = make_uint2((KEY), (GIDX));                     \
            atomicAdd(&shist[((KEY) >> 20) - PIVOT_BIN], 1u);                 \
        }                                                                     \
        cnt += (unsigned)__popc(bal);                                         \
        if (cnt >= WBUF_FLUSH) {                                              \
            unsigned base;                                                    \
            if (lane == 0) base = atomicAdd(&g_ncand, cnt);                   \
            base = __shfl_sync(0xFFFFFFFFu, base, 0);                         \
            for (unsigned q = lane; q < cnt; q += 32u) {                      \
                unsigned p = base + q;                                        \
                if (p < CAP) g_cand[p] = wbuf[w][q];                          \
            }                                                                 \
            cnt = 0u;                                                         \
        }                                                                     \
    }                                                                         \
} while (0)

// Per-float4: one cheap pre-ballot on max key; slow path only if any lane hits.
#define PROC4(V, GB0, ACT) do {                                               \
    unsigned kx = f2key(__float_as_uint((V).x));                              \
    unsigned ky = f2key(__float_as_uint((V).y));                              \
    unsigned kz = f2key(__float_as_uint((V).z));                              \
    unsigned kw = f2key(__float_as_uint((V).w));                              \
    unsigned kmax = max(max(kx, ky), max(kz, kw));                            \
    unsigned anyb = __ballot_sync(0xFFFFFFFFu, (ACT) && kmax >= PIVOT_KEY);   \
    if (anyb) {                                                               \
        bool a = (ACT);                                                       \
        KS_PUSH(kx, (GB0) + 0u, a && kx >= PIVOT_KEY);                        \
        KS_PUSH(ky, (GB0) + 1u, a && ky >= PIVOT_KEY);                        \
        KS_PUSH(kz, (GB0) + 2u, a && kz >= PIVOT_KEY);                        \
        KS_PUSH(kw, (GB0) + 3u, a && kw >= PIVOT_KEY);                        \
    }                                                                         \
} while (0)

    for (int t = blockIdx.x; t < T; t += gridDim.x) {
        float4* ot = (float4*)(out + (size_t)t * F);
        const int per = f4 >> 3;
        const int ws = w * per;
        const int we = (w == 7) ? f4 : ws + per;
        if (mask[t] == 0) {                      // masked: pure write stream
            for (int i = ws + lane; i < we; i += 32) __stcs(&ot[i], z4);
            continue;
        }
        const float4* xt = (const float4*)(x + (size_t)t * F);
        const unsigned tbase = (unsigned)t * (unsigned)F;
        int i = ws;
        for (; i + 128 <= we; i += 128) {
            float4 v[4];
#pragma unroll
            for (int j = 0; j < 4; j++) v[j] = __ldcs(&xt[i + j * 32 + lane]);
#pragma unroll
            for (int j = 0; j < 4; j++) __stcs(&ot[i + j * 32 + lane], z4);
#pragma unroll
            for (int j = 0; j < 4; j++) {
                const unsigned gb0 = tbase + (unsigned)((i + j * 32 + lane) << 2);
                PROC4(v[j], gb0, true);
            }
        }
        for (; i < we; i += 32) {
            const int ii = i + lane;
            const bool a = ii < we;
            float4 v = a ? __ldcs(&xt[ii]) : z4;
            if (a) __stcs(&ot[ii], z4);
            const unsigned gb0 = tbase + (unsigned)(ii << 2);
            PROC4(v, gb0, a);
        }
    }
#undef PROC4
#undef KS_PUSH

    // combined block flush: one global atomic for all 8 warp buffers
    if (lane == 0) wc[w] = cnt;
    __syncthreads();
    if (tid == 0) {
        unsigned s = 0;
        for (int q = 0; q < 8; q++) { unsigned c = wc[q]; wc[q] = s; s += c; }
        gbs = s ? atomicAdd(&g_ncand, s) : 0u;
    }
    __syncthreads();
    {
        const unsigned base = gbs + wc[w];
        for (unsigned q = lane; q < cnt; q += 32u) {
            unsigned p = base + q;
            if (p < CAP) g_cand[p] = wbuf[w][q];
        }
    }
    __syncthreads();
    for (int i = tid; i < NH; i += blockDim.x) {
        unsigned v = shist[i];
        if (v) atomicAdd(&g_hist[PIVOT_BIN + i], v);
    }
}

// --------------- K2FB: find boundary bin; exact fallback if pivot failed
__global__ void k2fb(const float* __restrict__ x,
                     const int* __restrict__ mask, int T, int F,
                     unsigned ktot) {
    __shared__ unsigned part[1024];
    __shared__ unsigned sh[NBIN];
    __shared__ int s_b1;
    const int tid = threadIdx.x;
    const int bd = blockDim.x;
    unsigned nc = g_ncand;

    if (nc >= ktot && nc <= CAP) {
        // ---- fast path: suffix scan of the pivot histogram ----
        unsigned own = (tid < NH) ? g_hist[PIVOT_BIN + tid] : 0u;
        part[tid] = own;
        __syncthreads();
        for (int off = 1; off < 1024; off <<= 1) {
            unsigned v = (tid + off < 1024) ? part[tid + off] : 0u;
            __syncthreads();
            part[tid] += v;
            __syncthreads();
        }
        unsigned above = part[tid] - own;
        if (own && above < ktot && above + own >= ktot) {
            g_b1 = PIVOT_BIN + tid;
            g_need = ktot - above;
        }
        return;
    }

    // ---- exact fallback (never taken for in-distribution inputs) ----
    for (int i = tid; i < NBIN; i += bd) sh[i] = 0u;
    __syncthreads();
    const int f4 = F >> 2;
    for (int t = 0; t < T; t++) {
        if (mask[t] == 0) continue;
        const float4* xt = (const float4*)(x + (size_t)t * F);
        for (int i = tid; i < f4; i += bd) {
            float4 v = xt[i];
            atomicAdd(&sh[f2key(__float_as_uint(v.x)) >> 20], 1u);
            atomicAdd(&sh[f2key(__float_as_uint(v.y)) >> 20], 1u);
            atomicAdd(&sh[f2key(__float_as_uint(v.z)) >> 20], 1u);
            atomicAdd(&sh[f2key(__float_as_uint(v.w)) >> 20], 1u);
        }
    }
    __syncthreads();
    if (tid == 0) {
        unsigned cum = 0u; int b1 = -1; unsigned need = 0u;
        for (int d = NBIN - 1; d >= 0; d--) {
            cum += sh[d];
            if (cum >= ktot) { b1 = d; need = ktot - (cum - sh[d]); break; }
        }
        if (b1 < 0) { b1 = 0; need = sh[0]; }   // fewer eligible than k
        s_b1 = b1;
        g_b1 = b1; g_need = need; g_ncand = 0u;
    }
    __syncthreads();
    const unsigned kmin = ((unsigned)s_b1) << 20;
    for (int t = 0; t < T; t++) {
        if (mask[t] == 0) continue;
        const float4* xt = (const float4*)(x + (size_t)t * F);
        const unsigned tbase = (unsigned)t * (unsigned)F;
        for (int i = tid; i < f4; i += bd) {
            float4 v = xt[i];
            const unsigned gb0 = tbase + ((unsigned)i << 2);
            const float* vp = (const float*)&v;
#pragma unroll
            for (int e = 0; e < 4; e++) {
                unsigned key = f2key(__float_as_uint(vp[e]));
                if (key >= kmin) {
                    unsigned p = atomicAdd(&g_ncand, 1u);
                    if (p < CAP) g_cand[p] = make_uint2(key, gb0 + (unsigned)e);
                }
            }
        }
    }
}

// ---------------- K4a: barrier-free split (scatter winners, compact bin b1)
__global__ void k4a_split(float* __restrict__ out) {
    const int tid = threadIdx.x;
    const int lane = tid & 31;
    const unsigned b1 = (unsigned)g_b1;
    const unsigned nc = min(g_ncand, CAP);
    const unsigned wstart = ((unsigned)blockIdx.x * blockDim.x + tid - lane);
    const unsigned stride = (unsigned)blockDim.x * gridDim.x;
    unsigned lmin = 0xFFFFFFFFu;

    // warp-uniform trip count: all lanes share 'base'
    for (unsigned base = wstart; base < nc; base += stride) {
        const unsigned i = base + lane;
        const bool valid = i < nc;
        uint2 c = valid ? g_cand[i] : make_uint2(0u, 0u);
        const unsigned bin = c.x >> 20;
        if (valid && bin > b1) {
            out[c.y] = fmaxf(key2f(c.x), 0.f);
            if (c.x > KEY_ZERO) lmin = min(lmin, c.x);
        }
        const bool isb = valid && (bin == b1);
        unsigned bal = __ballot_sync(0xFFFFFFFFu, isb);
        if (bal) {
            unsigned bse;
            if (lane == 0) bse = atomicAdd(&g_ncand2, (unsigned)__popc(bal));
            bse = __shfl_sync(0xFFFFFFFFu, bse, 0);
            if (isb) {
                unsigned r = __popc(bal & ((1u << lane) - 1u));
                unsigned p = bse + r;
                if (p < CAP2) g_cand2[p] = c;
                atomicAdd(&g_h2[(c.x >> 12) & 255u], 1u);
            }
        }
    }
    // warp-reduce min, then one global atomic per warp
#pragma unroll
    for (int off = 16; off > 0; off >>= 1)
        lmin = min(lmin, __shfl_xor_sync(0xFFFFFFFFu, lmin, off));
    if (lane == 0 && lmin != 0xFFFFFFFFu) atomicMin(&g_minpos, lmin);
}

// ------ K4b: finish select in bin b1, ties, EMA threshold, state reset
__global__ void k4b_final(const float* __restrict__ thr_in,
                          float* __restrict__ out, int n, int out_size) {
    __shared__ unsigned h[256];
    __shared__ unsigned s_sel, s_need, s_tiecnt, s_minpos;
    __shared__ unsigned tie_idx[MAXTIE];
    const int tid = threadIdx.x;
    const int bd = blockDim.x;
    const int b1 = g_b1;
    unsigned need = g_need;
    const unsigned nc2 = min(g_ncand2, CAP2);
    unsigned ck = 0u;
    bool have = (b1 >= 0) && need > 0u && nc2 > 0u;

    if (have) {
        if (tid == 0) {
            unsigned cum = 0u; s_sel = 0u; s_need = need;
            for (int d = 255; d >= 0; d--) {
                unsigned hv = g_h2[d];
                cum += hv;
                if (cum >= need) { s_sel = (unsigned)d; s_need = need - (cum - hv); break; }
            }
        }
        __syncthreads();
        unsigned prefix = ((unsigned)b1 << 20) | (s_sel << 12);
        unsigned pmask = 0xFFFFF000u;
        need = s_need;

        const int shifts[2] = {4, 0};
        const unsigned widths[2] = {256u, 16u};
#pragma unroll
        for (int lev = 0; lev < 2; lev++) {
            const int sh = shifts[lev];
            const unsigned w = widths[lev];
            for (unsigned d = tid; d < w; d += bd) h[d] = 0u;
            __syncthreads();
            for (unsigned i = tid; i < nc2; i += bd) {
                unsigned key = g_cand2[i].x;
                if ((key & pmask) == prefix) atomicAdd(&h[(key >> sh) & (w - 1u)], 1u);
            }
            __syncthreads();
            if (tid == 0) {
                unsigned cum = 0u; s_sel = 0u; s_need = need;
                for (int d = (int)w - 1; d >= 0; d--) {
                    cum += h[d];
                    if (cum >= need) { s_sel = (unsigned)d; s_need = need - (cum - h[d]); break; }
                }
            }
            __syncthreads();
            prefix |= s_sel << sh;
            pmask |= (w - 1u) << sh;
            need = s_need;
            __syncthreads();
        }
        ck = prefix;

        if (tid == 0) { s_tiecnt = 0u; s_minpos = 0xFFFFFFFFu; }
        __syncthreads();
        unsigned lmin = 0xFFFFFFFFu;
        for (unsigned i = tid; i < nc2; i += bd) {
            uint2 c = g_cand2[i];
            if (c.x > ck) {
                out[c.y] = fmaxf(key2f(c.x), 0.f);
                if (c.x > KEY_ZERO) lmin = min(lmin, c.x);
            } else if (c.x == ck) {
                unsigned p = atomicAdd(&s_tiecnt, 1u);
                if (p < MAXTIE) tie_idx[p] = c.y;
            }
        }
        atomicMin(&s_minpos, lmin);
        __syncthreads();
        unsigned tcnt = s_tiecnt;
        const float cv = fmaxf(key2f(ck), 0.f);
        if (tcnt <= (unsigned)MAXTIE) {
            for (unsigned i = tid; i < tcnt; i += bd) {
                unsigned mi = tie_idx[i];
                unsigned rank = 0u;
                for (unsigned j = 0; j < tcnt; j++) rank += (tie_idx[j] < mi) ? 1u : 0u;
                if (rank < need) out[mi] = cv;
            }
        } else {
            for (unsigned i = tid; i < need && i < (unsigned)MAXTIE; i += bd)
                out[tie_idx[i]] = cv;
        }
        __syncthreads();
    }

    if (tid == 0) {
        unsigned mp = g_minpos;
        if (have) {
            mp = min(mp, s_minpos);
            if (need > 0u && ck > KEY_ZERO) mp = min(mp, ck);
        }
        float thr = thr_in[0];
        float res = thr;
        if (mp != 0xFFFFFFFFu) res = 0.99f * thr + 0.01f * key2f(mp);
        out[out_size - 1] = res;
    }
    // zero any slack between data and threshold slot (harness poisons d_out)
    for (int i = n + tid; i < out_size - 1; i += bd) out[i] = 0.f;

    // ------------- reset persistent state for next graph replay -------------
    __syncthreads();
    for (int i = tid; i < NBIN; i += bd) g_hist[i] = 0u;
    for (int i = tid; i < 256; i += bd) g_h2[i] = 0u;
    if (tid == 0) {
        g_b1 = -1; g_need = 0u; g_ncand = 0u; g_ncand2 = 0u;
        g_flag = 0u; g_minpos = 0xFFFFFFFFu;
    }
}

// ---------------------------------------------------------------------------
extern "C" void kernel_launch(void* const* d_in, const int* in_sizes, int n_in,
                              void* d_out, int out_size) {
    const float* x = (const float*)d_in[0];
    const int* mask = (const int*)d_in[1];
    const float* thr = (const float*)d_in[2];
    float* out = (float*)d_out;

    const int n = in_sizes[0];
    const int T = in_sizes[1];
    const int F = n / T;
    const unsigned ktot = 32u * (unsigned)T;

    int gs = T < 2048 ? T : 2048;

    kms_stream<<<gs, 256>>>(x, mask, out, T, F);
    k2fb<<<1, 1024>>>(x, mask, T, F, ktot);
    k4a_split<<<256, 256>>>(out);
    k4b_final<<<1, 1024>>>(thr, out, n, out_size);
}

// round 6
// speedup vs baseline: 1.4709x; 1.4709x over previous
#include <cuda_runtime.h>
#include <stdint.h>

// ---------------------------------------------------------------------------
// BatchTopK: global top-(32*T) over masked [B,S,F], scatter relu'd winners,
// EMA threshold. 6-launch pipeline (no single-block heavy work):
//   KMS  : fused stream — zero output, read eligible x once, warp-ballot
//          compaction of keys >= pivot(2.25) + 1023-bin histogram (top-12 bits)
//   K2FB : 1 block — suffix-scan hist -> b1 + need; exact fallback if pivot
//          assumption failed (dormant)
//   K4a  : grid, barrier-free: bin>b1 -> scatter winners; bin==b1 -> cand2 +
//          12-bit sub-histogram g_h3[(key>>8)&0xFFF]
//   K4b  : 1 block, tiny: suffix-scan g_h3 -> 24-bit prefix P24 + need3
//   K4c  : grid: key>>8 > P24 -> scatter winners; == P24 -> compact to cand3
//   K4d  : 1 block, tiny: exact select among cand3 (low 8 bits), ties by
//          lowest index, EMA threshold, reset ALL state for next graph replay
// ---------------------------------------------------------------------------

#define NBIN 4096
#define PIVOT_KEY 0xC0100000u   // f2key(2.25f)
#define PIVOT_BIN 3073          // PIVOT_KEY >> 20
#define NH (NBIN - PIVOT_BIN)   // 1023 hist bins
#define KEY_ZERO  0x80000000u   // f2key(+0.0f)
#define CAP  (1u << 22)
#define CAP2 (1u << 20)
#define CAP3 4096
#define MAXTIE 4096
#define WBUF_CAP 96
#define WBUF_FLUSH 64

__device__ unsigned g_hist[NBIN];     // KMS: top-12-bit histogram (pivot range)
__device__ unsigned g_h3[NBIN];       // K4a: 12-bit sub-histogram of bin b1
__device__ int      g_b1 = -1;
__device__ unsigned g_need;
__device__ unsigned g_s24;            // 12-bit sub-prefix chosen by K4b
__device__ unsigned g_need3;
__device__ unsigned g_ncand;
__device__ unsigned g_ncand2;
__device__ unsigned g_ncand3;
__device__ unsigned g_minpos = 0xFFFFFFFFu;
__device__ uint2    g_cand[CAP];
__device__ uint2    g_cand2[CAP2];
__device__ uint2    g_cand3[CAP3];

__device__ __forceinline__ unsigned f2key(unsigned u) {
    unsigned m = ((unsigned)((int)u >> 31)) | 0x80000000u;
    return u ^ m;
}
__device__ __forceinline__ float key2f(unsigned k) {
    unsigned u = (k & 0x80000000u) ? (k ^ 0x80000000u) : ~k;
    return __uint_as_float(u);
}

// ------------------------- KMS: fused zero + scan + compact + histogram
// blockDim MUST be 256 (8 warps). (R4 version — known good.)
__global__ void kms_stream(const float* __restrict__ x,
                           const int* __restrict__ mask,
                           float* __restrict__ out, int T, int F) {
    __shared__ unsigned shist[NH];
    __shared__ uint2 wbuf[8][WBUF_CAP];
    __shared__ unsigned wc[8];
    __shared__ unsigned gbs;
    const int tid = threadIdx.x;
    const int lane = tid & 31;
    const int w = tid >> 5;
    for (int i = tid; i < NH; i += blockDim.x) shist[i] = 0u;
    __syncthreads();

    const int f4 = F >> 2;
    const float4 z4 = make_float4(0.f, 0.f, 0.f, 0.f);
    unsigned cnt = 0u;   // warp-uniform count in wbuf[w]

#define KS_PUSH(VAL, GIDX, ACT) do {                                          \
    unsigned key = f2key(__float_as_uint(VAL));                               \
    bool is = (ACT) && (key >= PIVOT_KEY);                                    \
    unsigned bal = __ballot_sync(0xFFFFFFFFu, is);                            \
    if (bal) {                                                                \
        if (is) {                                                             \
            unsigned r = __popc(bal & ((1u << lane) - 1u));                   \
            wbuf[w][cnt + r] = make_uint2(key, (GIDX));                       \
            atomicAdd(&shist[(key >> 20) - PIVOT_BIN], 1u);                   \
        }                                                                     \
        cnt += (unsigned)__popc(bal);                                         \
        if (cnt >= WBUF_FLUSH) {                                              \
            unsigned base;                                                    \
            if (lane == 0) base = atomicAdd(&g_ncand, cnt);                   \
            base = __shfl_sync(0xFFFFFFFFu, base, 0);                         \
            for (unsigned q = lane; q < cnt; q += 32u) {                      \
                unsigned p = base + q;                                        \
                if (p < CAP) g_cand[p] = wbuf[w][q];                          \
            }                                                                 \
            cnt = 0u;                                                         \
        }                                                                     \
    }                                                                         \
} while (0)

    for (int t = blockIdx.x; t < T; t += gridDim.x) {
        float4* ot = (float4*)(out + (size_t)t * F);
        const int per = f4 >> 3;
        const int ws = w * per;
        const int we = (w == 7) ? f4 : ws + per;
        if (mask[t] == 0) {                      // masked: pure write stream
            for (int i = ws + lane; i < we; i += 32) ot[i] = z4;
            continue;
        }
        const float4* xt = (const float4*)(x + (size_t)t * F);
        const unsigned tbase = (unsigned)t * (unsigned)F;
        int i = ws;
        for (; i + 128 <= we; i += 128) {
            float4 v[4];
#pragma unroll
            for (int j = 0; j < 4; j++) v[j] = xt[i + j * 32 + lane];
#pragma unroll
            for (int j = 0; j < 4; j++) ot[i + j * 32 + lane] = z4;
#pragma unroll
            for (int j = 0; j < 4; j++) {
                const unsigned gb0 = tbase + (unsigned)((i + j * 32 + lane) << 2);
                KS_PUSH(v[j].x, gb0 + 0u, true);
                KS_PUSH(v[j].y, gb0 + 1u, true);
                KS_PUSH(v[j].z, gb0 + 2u, true);
                KS_PUSH(v[j].w, gb0 + 3u, true);
            }
        }
        for (; i < we; i += 32) {
            const int ii = i + lane;
            const bool a = ii < we;
            float4 v = a ? xt[ii] : z4;
            if (a) ot[ii] = z4;
            const unsigned gb0 = tbase + (unsigned)(ii << 2);
            KS_PUSH(v.x, gb0 + 0u, a);
            KS_PUSH(v.y, gb0 + 1u, a);
            KS_PUSH(v.z, gb0 + 2u, a);
            KS_PUSH(v.w, gb0 + 3u, a);
        }
    }
#undef KS_PUSH

    if (lane == 0) wc[w] = cnt;
    __syncthreads();
    if (tid == 0) {
        unsigned s = 0;
        for (int q = 0; q < 8; q++) { unsigned c = wc[q]; wc[q] = s; s += c; }
        gbs = s ? atomicAdd(&g_ncand, s) : 0u;
    }
    __syncthreads();
    {
        const unsigned base = gbs + wc[w];
        for (unsigned q = lane; q < cnt; q += 32u) {
            unsigned p = base + q;
            if (p < CAP) g_cand[p] = wbuf[w][q];
        }
    }
    __syncthreads();
    for (int i = tid; i < NH; i += blockDim.x) {
        unsigned v = shist[i];
        if (v) atomicAdd(&g_hist[PIVOT_BIN + i], v);
    }
}

// --------------- K2FB: find boundary bin; exact fallback if pivot failed
__global__ void k2fb(const float* __restrict__ x,
                     const int* __restrict__ mask, int T, int F,
                     unsigned ktot) {
    __shared__ unsigned part[1024];
    __shared__ unsigned sh[NBIN];
    __shared__ int s_b1;
    const int tid = threadIdx.x;
    const int bd = blockDim.x;
    unsigned nc = g_ncand;

    if (nc >= ktot && nc <= CAP) {
        unsigned own = (tid < NH) ? g_hist[PIVOT_BIN + tid] : 0u;
        part[tid] = own;
        __syncthreads();
        for (int off = 1; off < 1024; off <<= 1) {
            unsigned v = (tid + off < 1024) ? part[tid + off] : 0u;
            __syncthreads();
            part[tid] += v;
            __syncthreads();
        }
        unsigned above = part[tid] - own;
        if (own && above < ktot && above + own >= ktot) {
            g_b1 = PIVOT_BIN + tid;
            g_need = ktot - above;
        }
        return;
    }

    // ---- exact fallback (dormant for in-distribution inputs) ----
    for (int i = tid; i < NBIN; i += bd) sh[i] = 0u;
    __syncthreads();
    const int f4 = F >> 2;
    for (int t = 0; t < T; t++) {
        if (mask[t] == 0) continue;
        const float4* xt = (const float4*)(x + (size_t)t * F);
        for (int i = tid; i < f4; i += bd) {
            float4 v = xt[i];
            atomicAdd(&sh[f2key(__float_as_uint(v.x)) >> 20], 1u);
            atomicAdd(&sh[f2key(__float_as_uint(v.y)) >> 20], 1u);
            atomicAdd(&sh[f2key(__float_as_uint(v.z)) >> 20], 1u);
            atomicAdd(&sh[f2key(__float_as_uint(v.w)) >> 20], 1u);
        }
    }
    __syncthreads();
    if (tid == 0) {
        unsigned cum = 0u; int b1 = -1; unsigned need = 0u;
        for (int d = NBIN - 1; d >= 0; d--) {
            cum += sh[d];
            if (cum >= ktot) { b1 = d; need = ktot - (cum - sh[d]); break; }
        }
        if (b1 < 0) { b1 = 0; need = sh[0]; }   // fewer eligible than k
        s_b1 = b1;
        g_b1 = b1; g_need = need; g_ncand = 0u;
    }
    __syncthreads();
    const unsigned kmin = ((unsigned)s_b1) << 20;
    for (int t = 0; t < T; t++) {
        if (mask[t] == 0) continue;
        const float4* xt = (const float4*)(x + (size_t)t * F);
        const unsigned tbase = (unsigned)t * (unsigned)F;
        for (int i = tid; i < f4; i += bd) {
            float4 v = xt[i];
            const unsigned gb0 = tbase + ((unsigned)i << 2);
            const float* vp = (const float*)&v;
#pragma unroll
            for (int e = 0; e < 4; e++) {
                unsigned key = f2key(__float_as_uint(vp[e]));
                if (key >= kmin) {
                    unsigned p = atomicAdd(&g_ncand, 1u);
                    if (p < CAP) g_cand[p] = make_uint2(key, gb0 + (unsigned)e);
                }
            }
        }
    }
}

// ------- K4a: barrier-free split (scatter winners, compact + sub-hist b1)
__global__ void k4a_split(float* __restrict__ out) {
    const int tid = threadIdx.x;
    const int lane = tid & 31;
    const unsigned b1 = (unsigned)g_b1;
    const unsigned nc = min(g_ncand, CAP);
    const unsigned wstart = ((unsigned)blockIdx.x * blockDim.x + tid - lane);
    const unsigned stride = (unsigned)blockDim.x * gridDim.x;
    unsigned lmin = 0xFFFFFFFFu;

    for (unsigned base = wstart; base < nc; base += stride) {
        const unsigned i = base + lane;
        const bool valid = i < nc;
        uint2 c = valid ? g_cand[i] : make_uint2(0u, 0u);
        const unsigned bin = c.x >> 20;
        if (valid && bin > b1) {
            out[c.y] = fmaxf(key2f(c.x), 0.f);
            if (c.x > KEY_ZERO) lmin = min(lmin, c.x);
        }
        const bool isb = valid && (bin == b1);
        unsigned bal = __ballot_sync(0xFFFFFFFFu, isb);
        if (bal) {
            unsigned bse;
            if (lane == 0) bse = atomicAdd(&g_ncand2, (unsigned)__popc(bal));
            bse = __shfl_sync(0xFFFFFFFFu, bse, 0);
            if (isb) {
                unsigned r = __popc(bal & ((1u << lane) - 1u));
                unsigned p = bse + r;
                if (p < CAP2) {
                    g_cand2[p] = c;
                    atomicAdd(&g_h3[(c.x >> 8) & 0xFFFu], 1u);
                }
            }
        }
    }
#pragma unroll
    for (int off = 16; off > 0; off >>= 1)
        lmin = min(lmin, __shfl_xor_sync(0xFFFFFFFFu, lmin, off));
    if (lane == 0 && lmin != 0xFFFFFFFFu) atomicMin(&g_minpos, lmin);
}

// ----------- K4b: suffix-scan g_h3 -> 24-bit prefix (s24) + need3
__global__ void k4b_scan() {
    __shared__ unsigned part[1024];
    const int tid = threadIdx.x;
    if (g_b1 < 0) return;
    const unsigned need = g_need;
    if (need == 0u) return;

    unsigned h[4]; unsigned own = 0u;
#pragma unroll
    for (int j = 0; j < 4; j++) { h[j] = g_h3[tid * 4 + j]; own += h[j]; }
    part[tid] = own;
    __syncthreads();
    for (int off = 1; off < 1024; off <<= 1) {
        unsigned v = (tid + off < 1024) ? part[tid + off] : 0u;
        __syncthreads();
        part[tid] += v;
        __syncthreads();
    }
    unsigned above = part[tid] - own;
    unsigned cum = above;
    for (int j = 3; j >= 0; j--) {
        cum += h[j];
        if (cum >= need && (cum - h[j]) < need) {
            g_s24 = (unsigned)(tid * 4 + j);
            g_need3 = need - (cum - h[j]);
        }
    }
}

// ------ K4c: grid — scatter sub-prefix winners, compact exact matches
__global__ void k4c_split(float* __restrict__ out) {
    const int tid = threadIdx.x;
    const int lane = tid & 31;
    if (g_b1 < 0) return;
    const unsigned P24 = (((unsigned)g_b1) << 12) | g_s24;
    const unsigned nc2 = min(g_ncand2, CAP2);
    const unsigned wstart = ((unsigned)blockIdx.x * blockDim.x + tid - lane);
    const unsigned stride = (unsigned)blockDim.x * gridDim.x;
    unsigned lmin = 0xFFFFFFFFu;

    for (unsigned base = wstart; base < nc2; base += stride) {
        const unsigned i = base + lane;
        const bool valid = i < nc2;
        uint2 c = valid ? g_cand2[i] : make_uint2(0u, 0u);
        const unsigned p24 = c.x >> 8;
        if (valid && p24 > P24) {
            out[c.y] = fmaxf(key2f(c.x), 0.f);
            if (c.x > KEY_ZERO) lmin = min(lmin, c.x);
        }
        const bool ism = valid && (p24 == P24);
        unsigned bal = __ballot_sync(0xFFFFFFFFu, ism);
        if (bal) {
            unsigned bse;
            if (lane == 0) bse = atomicAdd(&g_ncand3, (unsigned)__popc(bal));
            bse = __shfl_sync(0xFFFFFFFFu, bse, 0);
            if (ism) {
                unsigned r = __popc(bal & ((1u << lane) - 1u));
                unsigned p = bse + r;
                if (p < CAP3) g_cand3[p] = c;
            }
        }
    }
#pragma unroll
    for (int off = 16; off > 0; off >>= 1)
        lmin = min(lmin, __shfl_xor_sync(0xFFFFFFFFu, lmin, off));
    if (lane == 0 && lmin != 0xFFFFFFFFu) atomicMin(&g_minpos, lmin);
}

// -- K4d: exact select among cand3 (low 8 bits), ties, threshold, reset
__global__ void k4d_final(const float* __restrict__ thr_in,
                          float* __restrict__ out, int n, int out_size) {
    __shared__ unsigned h[256];
    __shared__ unsigned s_c8, s_need4, s_tiecnt, s_minpos;
    __shared__ unsigned tie_idx[MAXTIE];
    const int tid = threadIdx.x;
    const int bd = blockDim.x;
    const unsigned need3 = g_need3;
    const unsigned nc3 = min(g_ncand3, (unsigned)CAP3);
    unsigned ck = 0u;
    unsigned need4 = 0u;
    bool have = (g_b1 >= 0) && need3 > 0u && nc3 > 0u;

    if (have) {
        const unsigned P24 = (((unsigned)g_b1) << 12) | g_s24;
        for (int i = tid; i < 256; i += bd) h[i] = 0u;
        if (tid == 0) { s_tiecnt = 0u; s_minpos = 0xFFFFFFFFu; }
        __syncthreads();
        for (unsigned i = tid; i < nc3; i += bd)
            atomicAdd(&h[g_cand3[i].x & 255u], 1u);
        __syncthreads();
        if (tid == 0) {
            unsigned cum = 0u; s_c8 = 0u; s_need4 = need3;
            for (int d = 255; d >= 0; d--) {
                cum += h[d];
                if (cum >= need3) { s_c8 = (unsigned)d; s_need4 = need3 - (cum - h[d]); break; }
            }
        }
        __syncthreads();
        ck = (P24 << 8) | s_c8;
        need4 = s_need4;

        unsigned lmin = 0xFFFFFFFFu;
        for (unsigned i = tid; i < nc3; i += bd) {
            uint2 c = g_cand3[i];
            if (c.x > ck) {
                out[c.y] = fmaxf(key2f(c.x), 0.f);
                if (c.x > KEY_ZERO) lmin = min(lmin, c.x);
            } else if (c.x == ck) {
                unsigned p = atomicAdd(&s_tiecnt, 1u);
                if (p < MAXTIE) tie_idx[p] = c.y;
            }
        }
        atomicMin(&s_minpos, lmin);
        __syncthreads();
        const unsigned tcnt = min(s_tiecnt, (unsigned)MAXTIE);
        const float cv = fmaxf(key2f(ck), 0.f);
        // ties resolved by lowest flat index (matches sorted top_k order)
        for (unsigned i = tid; i < tcnt; i += bd) {
            unsigned mi = tie_idx[i];
            unsigned rank = 0u;
            for (unsigned j = 0; j < tcnt; j++) rank += (tie_idx[j] < mi) ? 1u : 0u;
            if (rank < need4) out[mi] = cv;
        }
        __syncthreads();
    }

    if (tid == 0) {
        unsigned mp = g_minpos;
        if (have) {
            mp = min(mp, s_minpos);
            if (need4 > 0u && ck > KEY_ZERO) mp = min(mp, ck);
        }
        float thr = thr_in[0];
        float res = thr;
        if (mp != 0xFFFFFFFFu) res = 0.99f * thr + 0.01f * key2f(mp);
        out[out_size - 1] = res;
    }
    // zero any slack between data and threshold slot (harness poisons d_out)
    for (int i = n + tid; i < out_size - 1; i += bd) out[i] = 0.f;

    // ------------- reset persistent state for next graph replay -------------
    __syncthreads();
    for (int i = tid; i < NBIN; i += bd) { g_hist[i] = 0u; g_h3[i] = 0u; }
    if (tid == 0) {
        g_b1 = -1; g_need = 0u; g_s24 = 0u; g_need3 = 0u;
        g_ncand = 0u; g_ncand2 = 0u; g_ncand3 = 0u;
        g_minpos = 0xFFFFFFFFu;
    }
}

// ---------------------------------------------------------------------------
extern "C" void kernel_launch(void* const* d_in, const int* in_sizes, int n_in,
                              void* d_out, int out_size) {
    const float* x = (const float*)d_in[0];
    const int* mask = (const int*)d_in[1];
    const float* thr = (const float*)d_in[2];
    float* out = (float*)d_out;

    const int n = in_sizes[0];
    const int T = in_sizes[1];
    const int F = n / T;
    const unsigned ktot = 32u * (unsigned)T;

    int gs = T < 2048 ? T : 2048;

    kms_stream<<<gs, 256>>>(x, mask, out, T, F);
    k2fb<<<1, 1024>>>(x, mask, T, F, ktot);
    k4a_split<<<256, 256>>>(out);
    k4b_scan<<<1, 1024>>>();
    k4c_split<<<128, 256>>>(out);
    k4d_final<<<1, 1024>>>(thr, out, n, out_size);
}

// round 7
// speedup vs baseline: 1.5216x; 1.0344x over previous
#include <cuda_runtime.h>
#include <stdint.h>

// ---------------------------------------------------------------------------
// BatchTopK: global top-(32*T) over masked [B,S,F], scatter relu'd winners,
// EMA threshold. 6-launch pipeline:
//   KMS  : persistent single-wave fused stream over quarter-token work items —
//          zero output, read eligible x once, warp-ballot compaction of keys
//          >= pivot(2.25) + 1023-bin histogram (top-12 bits)
//   K2FB : 1 block — warp-shuffle suffix scan -> b1 + need; exact fallback if
//          pivot assumption failed (dormant)
//   K4a  : grid, barrier-free: bin>b1 -> scatter winners; bin==b1 -> cand2 +
//          12-bit sub-histogram g_h3[(key>>8)&0xFFF]
//   K4b  : 1 block, warp-shuffle suffix scan of g_h3 -> 24-bit prefix + need3
//   K4c  : grid: key>>8 > P24 -> scatter winners; == P24 -> compact to cand3
//   K4d  : 1 block, tiny: exact select among cand3 (low 8 bits), ties by
//          lowest index, EMA threshold, reset ALL state for next graph replay
// ---------------------------------------------------------------------------

#define NBIN 4096
#define PIVOT_KEY 0xC0100000u   // f2key(2.25f)
#define PIVOT_BIN 3073          // PIVOT_KEY >> 20
#define NH (NBIN - PIVOT_BIN)   // 1023 hist bins
#define KEY_ZERO  0x80000000u   // f2key(+0.0f)
#define CAP  (1u << 22)
#define CAP2 (1u << 20)
#define CAP3 4096
#define MAXTIE 4096
#define WBUF_CAP 96
#define WBUF_FLUSH 64
#define SEG 4                   // work items per token in KMS

__device__ unsigned g_hist[NBIN];     // KMS: top-12-bit histogram (pivot range)
__device__ unsigned g_h3[NBIN];       // K4a: 12-bit sub-histogram of bin b1
__device__ int      g_b1 = -1;
__device__ unsigned g_need;
__device__ unsigned g_s24;            // 12-bit sub-prefix chosen by K4b
__device__ unsigned g_need3;
__device__ unsigned g_ncand;
__device__ unsigned g_ncand2;
__device__ unsigned g_ncand3;
__device__ unsigned g_minpos = 0xFFFFFFFFu;
__device__ uint2    g_cand[CAP];
__device__ uint2    g_cand2[CAP2];
__device__ uint2    g_cand3[CAP3];

__device__ __forceinline__ unsigned f2key(unsigned u) {
    unsigned m = ((unsigned)((int)u >> 31)) | 0x80000000u;
    return u ^ m;
}
__device__ __forceinline__ float key2f(unsigned k) {
    unsigned u = (k & 0x80000000u) ? (k ^ 0x80000000u) : ~k;
    return __uint_as_float(u);
}

// Warp-level inclusive suffix scan of 'v' (lane 0 ends with warp total).
__device__ __forceinline__ unsigned warp_suffix_incl(unsigned v, int lane) {
#pragma unroll
    for (int off = 1; off < 32; off <<= 1) {
        unsigned u = __shfl_down_sync(0xFFFFFFFFu, v, off);
        if (lane + off < 32) v += u;
    }
    return v;
}

// ------------------------- KMS: fused zero + scan + compact + histogram
// blockDim MUST be 256 (8 warps). Persistent single-wave grid.
__global__ void kms_stream(const float* __restrict__ x,
                           const int* __restrict__ mask,
                           float* __restrict__ out, int T, int F) {
    __shared__ unsigned shist[NH];
    __shared__ uint2 wbuf[8][WBUF_CAP];
    __shared__ unsigned wc[8];
    __shared__ unsigned gbs;
    const int tid = threadIdx.x;
    const int lane = tid & 31;
    const int w = tid >> 5;
    for (int i = tid; i < NH; i += blockDim.x) shist[i] = 0u;
    __syncthreads();

    const int f4 = F >> 2;
    const float4 z4 = make_float4(0.f, 0.f, 0.f, 0.f);
    unsigned cnt = 0u;   // warp-uniform count in wbuf[w]

#define KS_PUSH(VAL, GIDX, ACT) do {                                          \
    unsigned key = f2key(__float_as_uint(VAL));                               \
    bool is = (ACT) && (key >= PIVOT_KEY);                                    \
    unsigned bal = __ballot_sync(0xFFFFFFFFu, is);                            \
    if (bal) {                                                                \
        if (is) {                                                             \
            unsigned r = __popc(bal & ((1u << lane) - 1u));                   \
            wbuf[w][cnt + r] = make_uint2(key, (GIDX));                       \
            atomicAdd(&shist[(key >> 20) - PIVOT_BIN], 1u);                   \
        }                                                                     \
        cnt += (unsigned)__popc(bal);                                         \
        if (cnt >= WBUF_FLUSH) {                                              \
            unsigned base;                                                    \
            if (lane == 0) base = atomicAdd(&g_ncand, cnt);                   \
            base = __shfl_sync(0xFFFFFFFFu, base, 0);                         \
            for (unsigned q = lane; q < cnt; q += 32u) {                      \
                unsigned p = base + q;                                        \
                if (p < CAP) g_cand[p] = wbuf[w][q];                          \
            }                                                                 \
            cnt = 0u;                                                         \
        }                                                                     \
    }                                                                         \
} while (0)

    const int nitems = T * SEG;
    for (int it = blockIdx.x; it < nitems; it += gridDim.x) {
        const int t = it / SEG;
        const int sg = it - t * SEG;
        const int s0 = (int)(((long long)sg * f4) / SEG);
        const int s1 = (int)(((long long)(sg + 1) * f4) / SEG);
        const int len = s1 - s0;
        const int per = len >> 3;
        const int ws = s0 + w * per;
        const int we = (w == 7) ? s1 : ws + per;

        float4* ot = (float4*)(out + (size_t)t * F);
        if (mask[t] == 0) {                      // masked: pure write stream
            for (int i = ws + lane; i < we; i += 32) ot[i] = z4;
            continue;
        }
        const float4* xt = (const float4*)(x + (size_t)t * F);
        const unsigned tbase = (unsigned)t * (unsigned)F;
        int i = ws;
        for (; i + 128 <= we; i += 128) {
            float4 v[4];
#pragma unroll
            for (int j = 0; j < 4; j++) v[j] = xt[i + j * 32 + lane];
#pragma unroll
            for (int j = 0; j < 4; j++) ot[i + j * 32 + lane] = z4;
#pragma unroll
            for (int j = 0; j < 4; j++) {
                const unsigned gb0 = tbase + (unsigned)((i + j * 32 + lane) << 2);
                KS_PUSH(v[j].x, gb0 + 0u, true);
                KS_PUSH(v[j].y, gb0 + 1u, true);
                KS_PUSH(v[j].z, gb0 + 2u, true);
                KS_PUSH(v[j].w, gb0 + 3u, true);
            }
        }
        for (; i < we; i += 32) {
            const int ii = i + lane;
            const bool a = ii < we;
            float4 v = a ? xt[ii] : z4;
            if (a) ot[ii] = z4;
            const unsigned gb0 = tbase + (unsigned)(ii << 2);
            KS_PUSH(v.x, gb0 + 0u, a);
            KS_PUSH(v.y, gb0 + 1u, a);
            KS_PUSH(v.z, gb0 + 2u, a);
            KS_PUSH(v.w, gb0 + 3u, a);
        }
    }
#undef KS_PUSH

    if (lane == 0) wc[w] = cnt;
    __syncthreads();
    if (tid == 0) {
        unsigned s = 0;
        for (int q = 0; q < 8; q++) { unsigned c = wc[q]; wc[q] = s; s += c; }
        gbs = s ? atomicAdd(&g_ncand, s) : 0u;
    }
    __syncthreads();
    {
        const unsigned base = gbs + wc[w];
        for (unsigned q = lane; q < cnt; q += 32u) {
            unsigned p = base + q;
            if (p < CAP) g_cand[p] = wbuf[w][q];
        }
    }
    __syncthreads();
    for (int i = tid; i < NH; i += blockDim.x) {
        unsigned v = shist[i];
        if (v) atomicAdd(&g_hist[PIVOT_BIN + i], v);
    }
}

// --------------- K2FB: find boundary bin; exact fallback if pivot failed
__global__ void k2fb(const float* __restrict__ x,
                     const int* __restrict__ mask, int T, int F,
                     unsigned ktot) {
    __shared__ unsigned wsum[32], wsuf[32];
    __shared__ unsigned sh[NBIN];
    __shared__ int s_b1;
    const int tid = threadIdx.x;
    const int bd = blockDim.x;
    const int lane = tid & 31;
    const int wid = tid >> 5;
    unsigned nc = g_ncand;

    if (nc >= ktot && nc <= CAP) {
        // ---- fast path: warp-shuffle suffix scan of pivot histogram ----
        unsigned own = (tid < NH) ? g_hist[PIVOT_BIN + tid] : 0u;
        unsigned ws = warp_suffix_incl(own, lane);     // within-warp suffix
        if (lane == 0) wsum[wid] = ws;                 // warp total
        __syncthreads();
        if (wid == 0) {
            unsigned t = wsum[lane];
            unsigned ss = warp_suffix_incl(t, lane);
            wsuf[lane] = ss - t;                       // strictly-higher warps
        }
        __syncthreads();
        unsigned incl = ws + wsuf[wid];                // suffix incl. own bin
        unsigned above = incl - own;
        if (own && above < ktot && incl >= ktot) {
            g_b1 = PIVOT_BIN + tid;
            g_need = ktot - above;
        }
        return;
    }

    // ---- exact fallback (dormant for in-distribution inputs) ----
    for (int i = tid; i < NBIN; i += bd) sh[i] = 0u;
    __syncthreads();
    const int f4 = F >> 2;
    for (int t = 0; t < T; t++) {
        if (mask[t] == 0) continue;
        const float4* xt = (const float4*)(x + (size_t)t * F);
        for (int i = tid; i < f4; i += bd) {
            float4 v = xt[i];
            atomicAdd(&sh[f2key(__float_as_uint(v.x)) >> 20], 1u);
            atomicAdd(&sh[f2key(__float_as_uint(v.y)) >> 20], 1u);
            atomicAdd(&sh[f2key(__float_as_uint(v.z)) >> 20], 1u);
            atomicAdd(&sh[f2key(__float_as_uint(v.w)) >> 20], 1u);
        }
    }
    __syncthreads();
    if (tid == 0) {
        unsigned cum = 0u; int b1 = -1; unsigned need = 0u;
        for (int d = NBIN - 1; d >= 0; d--) {
            cum += sh[d];
            if (cum >= ktot) { b1 = d; need = ktot - (cum - sh[d]); break; }
        }
        if (b1 < 0) { b1 = 0; need = sh[0]; }   // fewer eligible than k
        s_b1 = b1;
        g_b1 = b1; g_need = need; g_ncand = 0u;
    }
    __syncthreads();
    const unsigned kmin = ((unsigned)s_b1) << 20;
    for (int t = 0; t < T; t++) {
        if (mask[t] == 0) continue;
        const float4* xt = (const float4*)(x + (size_t)t * F);
        const unsigned tbase = (unsigned)t * (unsigned)F;
        for (int i = tid; i < f4; i += bd) {
            float4 v = xt[i];
            const unsigned gb0 = tbase + ((unsigned)i << 2);
            const float* vp = (const float*)&v;
#pragma unroll
            for (int e = 0; e < 4; e++) {
                unsigned key = f2key(__float_as_uint(vp[e]));
                if (key >= kmin) {
                    unsigned p = atomicAdd(&g_ncand, 1u);
                    if (p < CAP) g_cand[p] = make_uint2(key, gb0 + (unsigned)e);
                }
            }
        }
    }
}

// ------- K4a: barrier-free split (scatter winners, compact + sub-hist b1)
__global__ void k4a_split(float* __restrict__ out) {
    const int tid = threadIdx.x;
    const int lane = tid & 31;
    const unsigned b1 = (unsigned)g_b1;
    const unsigned nc = min(g_ncand, CAP);
    const unsigned wstart = ((unsigned)blockIdx.x * blockDim.x + tid - lane);
    const unsigned stride = (unsigned)blockDim.x * gridDim.x;
    unsigned lmin = 0xFFFFFFFFu;

    for (unsigned base = wstart; base < nc; base += stride) {
        const unsigned i = base + lane;
        const bool valid = i < nc;
        uint2 c = valid ? g_cand[i] : make_uint2(0u, 0u);
        const unsigned bin = c.x >> 20;
        if (valid && bin > b1) {
            out[c.y] = fmaxf(key2f(c.x), 0.f);
            if (c.x > KEY_ZERO) lmin = min(lmin, c.x);
        }
        const bool isb = valid && (bin == b1);
        unsigned bal = __ballot_sync(0xFFFFFFFFu, isb);
        if (bal) {
            unsigned bse;
            if (lane == 0) bse = atomicAdd(&g_ncand2, (unsigned)__popc(bal));
            bse = __shfl_sync(0xFFFFFFFFu, bse, 0);
            if (isb) {
                unsigned r = __popc(bal & ((1u << lane) - 1u));
                unsigned p = bse + r;
                if (p < CAP2) {
                    g_cand2[p] = c;
                    atomicAdd(&g_h3[(c.x >> 8) & 0xFFFu], 1u);
                }
            }
        }
    }
#pragma unroll
    for (int off = 16; off > 0; off >>= 1)
        lmin = min(lmin, __shfl_xor_sync(0xFFFFFFFFu, lmin, off));
    if (lane == 0 && lmin != 0xFFFFFFFFu) atomicMin(&g_minpos, lmin);
}

// ----------- K4b: warp-shuffle suffix scan g_h3 -> 24-bit prefix + need3
__global__ void k4b_scan() {
    __shared__ unsigned wsum[32], wsuf[32];
    const int tid = threadIdx.x;
    const int lane = tid & 31;
    const int wid = tid >> 5;
    if (g_b1 < 0) return;
    const unsigned need = g_need;
    if (need == 0u) return;

    unsigned h[4]; unsigned own = 0u;
#pragma unroll
    for (int j = 0; j < 4; j++) { h[j] = g_h3[tid * 4 + j]; own += h[j]; }
    unsigned ws = warp_suffix_incl(own, lane);
    if (lane == 0) wsum[wid] = ws;
    __syncthreads();
    if (wid == 0) {
        unsigned t = wsum[lane];
        unsigned ss = warp_suffix_incl(t, lane);
        wsuf[lane] = ss - t;
    }
    __syncthreads();
    unsigned above = ws + wsuf[wid] - own;   // strictly above this thread's 4 bins
    unsigned cum = above;
    for (int j = 3; j >= 0; j--) {
        cum += h[j];
        if (cum >= need && (cum - h[j]) < need) {
            g_s24 = (unsigned)(tid * 4 + j);
            g_need3 = need - (cum - h[j]);
        }
    }
}

// ------ K4c: grid — scatter sub-prefix winners, compact exact matches
__global__ void k4c_split(float* __restrict__ out) {
    const int tid = threadIdx.x;
    const int lane = tid & 31;
    if (g_b1 < 0) return;
    const unsigned P24 = (((unsigned)g_b1) << 12) | g_s24;
    const unsigned nc2 = min(g_ncand2, CAP2);
    const unsigned wstart = ((unsigned)blockIdx.x * blockDim.x + tid - lane);
    const unsigned stride = (unsigned)blockDim.x * gridDim.x;
    unsigned lmin = 0xFFFFFFFFu;

    for (unsigned base = wstart; base < nc2; base += stride) {
        const unsigned i = base + lane;
        const bool valid = i < nc2;
        uint2 c = valid ? g_cand2[i] : make_uint2(0u, 0u);
        const unsigned p24 = c.x >> 8;
        if (valid && p24 > P24) {
            out[c.y] = fmaxf(key2f(c.x), 0.f);
            if (c.x > KEY_ZERO) lmin = min(lmin, c.x);
        }
        const bool ism = valid && (p24 == P24);
        unsigned bal = __ballot_sync(0xFFFFFFFFu, ism);
        if (bal) {
            unsigned bse;
            if (lane == 0) bse = atomicAdd(&g_ncand3, (unsigned)__popc(bal));
            bse = __shfl_sync(0xFFFFFFFFu, bse, 0);
            if (ism) {
                unsigned r = __popc(bal & ((1u << lane) - 1u));
                unsigned p = bse + r;
                if (p < CAP3) g_cand3[p] = c;
            }
        }
    }
#pragma unroll
    for (int off = 16; off > 0; off >>= 1)
        lmin = min(lmin, __shfl_xor_sync(0xFFFFFFFFu, lmin, off));
    if (lane == 0 && lmin != 0xFFFFFFFFu) atomicMin(&g_minpos, lmin);
}

// -- K4d: exact select among cand3 (low 8 bits), ties, threshold, reset
__global__ void k4d_final(const float* __restrict__ thr_in,
                          float* __restrict__ out, int n, int out_size) {
    __shared__ unsigned h[256];
    __shared__ unsigned s_c8, s_need4, s_tiecnt, s_minpos;
    __shared__ unsigned tie_idx[MAXTIE];
    const int tid = threadIdx.x;
    const int bd = blockDim.x;
    const unsigned need3 = g_need3;
    const unsigned nc3 = min(g_ncand3, (unsigned)CAP3);
    unsigned ck = 0u;
    unsigned need4 = 0u;
    bool have = (g_b1 >= 0) && need3 > 0u && nc3 > 0u;

    if (have) {
        const unsigned P24 = (((unsigned)g_b1) << 12) | g_s24;
        for (int i = tid; i < 256; i += bd) h[i] = 0u;
        if (tid == 0) { s_tiecnt = 0u; s_minpos = 0xFFFFFFFFu; }
        __syncthreads();
        for (unsigned i = tid; i < nc3; i += bd)
            atomicAdd(&h[g_cand3[i].x & 255u], 1u);
        __syncthreads();
        if (tid == 0) {
            unsigned cum = 0u; s_c8 = 0u; s_need4 = need3;
            for (int d = 255; d >= 0; d--) {
                cum += h[d];
                if (cum >= need3) { s_c8 = (unsigned)d; s_need4 = need3 - (cum - h[d]); break; }
            }
        }
        __syncthreads();
        ck = (P24 << 8) | s_c8;
        need4 = s_need4;

        unsigned lmin = 0xFFFFFFFFu;
        for (unsigned i = tid; i < nc3; i += bd) {
            uint2 c = g_cand3[i];
            if (c.x > ck) {
                out[c.y] = fmaxf(key2f(c.x), 0.f);
                if (c.x > KEY_ZERO) lmin = min(lmin, c.x);
            } else if (c.x == ck) {
                unsigned p = atomicAdd(&s_tiecnt, 1u);
                if (p < MAXTIE) tie_idx[p] = c.y;
            }
        }
        atomicMin(&s_minpos, lmin);
        __syncthreads();
        const unsigned tcnt = min(s_tiecnt, (unsigned)MAXTIE);
        const float cv = fmaxf(key2f(ck), 0.f);
        for (unsigned i = tid; i < tcnt; i += bd) {
            unsigned mi = tie_idx[i];
            unsigned rank = 0u;
            for (unsigned j = 0; j < tcnt; j++) rank += (tie_idx[j] < mi) ? 1u : 0u;
            if (rank < need4) out[mi] = cv;
        }
        __syncthreads();
    }

    if (tid == 0) {
        unsigned mp = g_minpos;
        if (have) {
            mp = min(mp, s_minpos);
            if (need4 > 0u && ck > KEY_ZERO) mp = min(mp, ck);
        }
        float thr = thr_in[0];
        float res = thr;
        if (mp != 0xFFFFFFFFu) res = 0.99f * thr + 0.01f * key2f(mp);
        out[out_size - 1] = res;
    }
    // zero any slack between data and threshold slot (harness poisons d_out)
    for (int i = n + tid; i < out_size - 1; i += bd) out[i] = 0.f;

    // ------------- reset persistent state for next graph replay -------------
    __syncthreads();
    for (int i = tid; i < NBIN; i += bd) { g_hist[i] = 0u; g_h3[i] = 0u; }
    if (tid == 0) {
        g_b1 = -1; g_need = 0u; g_s24 = 0u; g_need3 = 0u;
        g_ncand = 0u; g_ncand2 = 0u; g_ncand3 = 0u;
        g_minpos = 0xFFFFFFFFu;
    }
}

// ---------------------------------------------------------------------------
extern "C" void kernel_launch(void* const* d_in, const int* in_sizes, int n_in,
                              void* d_out, int out_size) {
    const float* x = (const float*)d_in[0];
    const int* mask = (const int*)d_in[1];
    const float* thr = (const float*)d_in[2];
    float* out = (float*)d_out;

    const int n = in_sizes[0];
    const int T = in_sizes[1];
    const int F = n / T;
    const unsigned ktot = 32u * (unsigned)T;

    const int nitems = T * SEG;
    int gs = 152 * 8;                       // single wave on 152 SMs
    if (gs > nitems) gs = nitems;

    kms_stream<<<gs, 256>>>(x, mask, out, T, F);
    k2fb<<<1, 1024>>>(x, mask, T, F, ktot);
    k4a_split<<<256, 256>>>(out);
    k4b_scan<<<1, 1024>>>();
    k4c_split<<<128, 256>>>(out);
    k4d_final<<<1, 1024>>>(thr, out, n, out_size);
}